// round 1
// baseline (speedup 1.0000x reference)
#include <cuda_runtime.h>
#include <math.h>

#define BB 64
#define SS 256
#define HH 768
#define G4 3072          // 4*H
#define TT 255           // decode steps
#define SLEN (2*SS+2)    // 514
#define WLEN (SS+1)      // 257

// ------------------- device scratch (BSS zero-initialized) -------------------
__device__ float g_gi_f[(size_t)SS*BB*G4];        // input gates fwd  [t][b][n]
__device__ float g_gi_b[(size_t)SS*BB*G4];        // input gates bwd  [t][b][n]
__device__ float g_lstm_out[(size_t)BB*SS*2*HH];  // [b][t][2H]
__device__ float g_pre1[(size_t)TT*BB*G4];        // x_prev @ subw_Wih.T + b  [t][b][n]
__device__ float g_sh[(size_t)BB*SLEN*HH];
__device__ float g_sc[(size_t)BB*SLEN*HH];
__device__ float g_wh[(size_t)BB*WLEN*HH];
__device__ float g_wc[(size_t)BB*WLEN*HH];
__device__ float g_hstate[4*BB*HH];               // [dir][parity][b][j]
__device__ float g_cstate[2*BB*HH];               // [dir][b][j]
__device__ float g_h1[BB*HH];
__device__ float g_c1[BB*HH];
__device__ float g_whbuf[BB*HH];
__device__ float g_ccur[TT*BB*2];
__device__ int   g_spa[TT*BB];
__device__ int   g_wpa[TT*BB];

__device__ __forceinline__ float sigf(float x){ return 1.f/(1.f+expf(-x)); }

// ------------------- zero the per-launch states -------------------
__global__ void zero_states()
{
    int stride = gridDim.x*blockDim.x;
    for (int i = blockIdx.x*blockDim.x+threadIdx.x; i < 4*BB*HH; i += stride) g_hstate[i]=0.f;
    for (int i = blockIdx.x*blockDim.x+threadIdx.x; i < 2*BB*HH; i += stride) g_cstate[i]=0.f;
}

// ------------------- precompute stack pointers from golds -------------------
__global__ void ptr_kernel(const int* __restrict__ golds)
{
    int b = threadIdx.x;
    if (b >= BB) return;
    int sp = 0, wp = 0;
    for (int t = 0; t < TT; t++) {
        g_spa[t*BB+b] = sp;
        g_wpa[t*BB+b] = wp;
        int g = golds[b*SS + t + 1];
        sp += (g==0) ? 1 : 2;   // subw_map = [1,2,2]
        wp += (g==0) ? 0 : 1;   // word_map = [0,1,1]
    }
}

// ------------------- generic big GEMM: C[r][n] = A_row(r) . W[n] + bias[n] ----
// row r = t*64 + b ; A row offset = (b*SS + t)*K ; C row stride = G4 (N=3072)
__global__ __launch_bounds__(256) void gemm_xw(
    const float* __restrict__ A, const float* __restrict__ W,
    const float* __restrict__ bias, float* __restrict__ C, int K)
{
    __shared__ float As[16][64];
    __shared__ float Ws[16][64];
    const int tid = threadIdx.x;
    const int bm = blockIdx.y << 6, bn = blockIdx.x << 6;
    const int tm = tid >> 4, tn = tid & 15;
    const int lrow = tid >> 2, lk4 = (tid & 3) << 2;
    const int r = bm + lrow;
    const float* arow = A + ((size_t)(r & 63) * SS + (r >> 6)) * K;
    const float* wrow = W + (size_t)(bn + lrow) * K;
    float acc[4][4] = {};
    for (int k0 = 0; k0 < K; k0 += 16) {
        float4 av = *(const float4*)(arow + k0 + lk4);
        float4 wv = *(const float4*)(wrow + k0 + lk4);
        __syncthreads();
        As[lk4+0][lrow]=av.x; As[lk4+1][lrow]=av.y; As[lk4+2][lrow]=av.z; As[lk4+3][lrow]=av.w;
        Ws[lk4+0][lrow]=wv.x; Ws[lk4+1][lrow]=wv.y; Ws[lk4+2][lrow]=wv.z; Ws[lk4+3][lrow]=wv.w;
        __syncthreads();
        #pragma unroll
        for (int kk = 0; kk < 16; kk++) {
            float4 a = *(const float4*)&As[kk][tm<<2];
            float4 w = *(const float4*)&Ws[kk][tn<<2];
            float aa[4]={a.x,a.y,a.z,a.w}, ww[4]={w.x,w.y,w.z,w.w};
            #pragma unroll
            for (int i=0;i<4;i++)
                #pragma unroll
                for (int j=0;j<4;j++) acc[i][j] += aa[i]*ww[j];
        }
    }
    #pragma unroll
    for (int i=0;i<4;i++) {
        int row = bm + (tm<<2) + i;
        #pragma unroll
        for (int j=0;j<4;j++) {
            int col = bn + (tn<<2) + j;
            C[(size_t)row*G4 + col] = acc[i][j] + bias[col];
        }
    }
}

// ------------------- shared 768-K accumulation helper -------------------
// block computes 64 batch x 16 j x 4 gates; thread (mg,jj) holds acc[4 batch][4 gate]
__device__ __forceinline__ void accum_seg(
    float acc[4][4], const float* __restrict__ srcrow, const float* __restrict__ wrow,
    float (*hs)[64], float (*ws)[64], int tid)
{
    const int lrow = tid >> 2, lk4 = (tid & 3) << 2;
    const int jj = tid & 15, mg = tid >> 4;
    for (int k0 = 0; k0 < HH; k0 += 32) {
        float4 h1v = *(const float4*)(srcrow + k0 + lk4);
        float4 h2v = *(const float4*)(srcrow + k0 + 16 + lk4);
        float4 w1v = *(const float4*)(wrow + k0 + lk4);
        float4 w2v = *(const float4*)(wrow + k0 + 16 + lk4);
        __syncthreads();
        hs[lk4+0][lrow]=h1v.x; hs[lk4+1][lrow]=h1v.y; hs[lk4+2][lrow]=h1v.z; hs[lk4+3][lrow]=h1v.w;
        hs[16+lk4+0][lrow]=h2v.x; hs[16+lk4+1][lrow]=h2v.y; hs[16+lk4+2][lrow]=h2v.z; hs[16+lk4+3][lrow]=h2v.w;
        ws[lk4+0][lrow]=w1v.x; ws[lk4+1][lrow]=w1v.y; ws[lk4+2][lrow]=w1v.z; ws[lk4+3][lrow]=w1v.w;
        ws[16+lk4+0][lrow]=w2v.x; ws[16+lk4+1][lrow]=w2v.y; ws[16+lk4+2][lrow]=w2v.z; ws[16+lk4+3][lrow]=w2v.w;
        __syncthreads();
        #pragma unroll
        for (int kk = 0; kk < 32; kk++) {
            float4 a = *(const float4*)&hs[kk][mg<<2];
            float4 w = *(const float4*)&ws[kk][jj<<2];
            float aa[4]={a.x,a.y,a.z,a.w}, wwv[4]={w.x,w.y,w.z,w.w};
            #pragma unroll
            for (int mi=0;mi<4;mi++)
                #pragma unroll
                for (int g=0;g<4;g++) acc[mi][g] += aa[mi]*wwv[g];
        }
    }
}

// ------------------- BiLSTM recurrent step (both directions) -------------------
__global__ __launch_bounds__(256) void lstm_step(int t,
    const float* __restrict__ Whh_f, const float* __restrict__ Whh_b)
{
    __shared__ float hs[32][64], ws[32][64];
    const int tid = threadIdx.x;
    const int dir = blockIdx.y;
    const int tt = dir ? (SS-1-t) : t;
    const int j0 = blockIdx.x << 4;
    const float* Whh = dir ? Whh_b : Whh_f;
    const float* gi = (dir ? g_gi_b : g_gi_f) + (size_t)tt*BB*G4;
    const float* hin = g_hstate + (size_t)(dir*2 + (t&1))*BB*HH;
    float* hout = g_hstate + (size_t)(dir*2 + ((t&1)^1))*BB*HH;
    float* cst = g_cstate + (size_t)dir*BB*HH;
    const int lrow = tid >> 2;
    const float* srcrow = hin + lrow*HH;
    const float* wrow = Whh + (size_t)((lrow&3)*HH + j0 + (lrow>>2)) * HH;
    float acc[4][4] = {};
    accum_seg(acc, srcrow, wrow, hs, ws, tid);
    const int jj = tid & 15, mg = tid >> 4;
    const int j = j0 + jj;
    #pragma unroll
    for (int mi=0; mi<4; mi++) {
        int b = (mg<<2) + mi;
        float vi = gi[b*G4 +           j] + acc[mi][0];
        float vf = gi[b*G4 +   HH +    j] + acc[mi][1];
        float vg = gi[b*G4 + 2*HH +    j] + acc[mi][2];
        float vo = gi[b*G4 + 3*HH +    j] + acc[mi][3];
        float c = sigf(vf)*cst[b*HH+j] + sigf(vi)*tanhf(vg);
        float h = sigf(vo)*tanhf(c);
        cst[b*HH+j] = c;
        hout[b*HH+j] = h;
        g_lstm_out[((size_t)b*SS + tt)*(2*HH) + dir*HH + j] = h;
    }
}

// ------------------- decode kernel A: subword cell (+ classifier for step t-1) --
__global__ __launch_bounds__(256) void decodeA(int t,
    const float* __restrict__ subw_Whh, const float* __restrict__ clsW,
    float* __restrict__ out)
{
    const int tid = threadIdx.x;
    if (blockIdx.x == 48) {           // classifier for previous step
        if (t == 0) return;
        if (tid < 128) {
            int b = tid >> 1, c = tid & 1;
            const float* w = clsW + c*(3*HH);       // wh part: cols [0,768)
            const float* hb = g_whbuf + b*HH;
            float s = g_ccur[(t-1)*BB*2 + (b<<1) + c];
            for (int k = 0; k < HH; k++) s += hb[k]*w[k];
            out[((size_t)b*SS + t)*2 + c] = s;      // position (t-1)+1 = t
        }
        return;
    }
    __shared__ float hs[32][64], ws[32][64];
    __shared__ int sp_s[BB];
    if (tid < BB) sp_s[tid] = g_spa[t*BB + tid];
    __syncthreads();
    const int j0 = blockIdx.x << 4;
    const float* gi = g_pre1 + (size_t)t*BB*G4;
    const int lrow = tid >> 2;
    const float* srcrow = g_sh + ((size_t)lrow*SLEN + sp_s[lrow]) * HH;
    const float* wrow = subw_Whh + (size_t)((lrow&3)*HH + j0 + (lrow>>2)) * HH;
    float acc[4][4] = {};
    accum_seg(acc, srcrow, wrow, hs, ws, tid);
    const int jj = tid & 15, mg = tid >> 4;
    const int j = j0 + jj;
    #pragma unroll
    for (int mi=0; mi<4; mi++) {
        int b = (mg<<2) + mi;
        int sp = sp_s[b];
        float vi = gi[b*G4 +        j] + acc[mi][0];
        float vf = gi[b*G4 + HH +   j] + acc[mi][1];
        float vg = gi[b*G4 + 2*HH + j] + acc[mi][2];
        float vo = gi[b*G4 + 3*HH + j] + acc[mi][3];
        float c = sigf(vf)*g_sc[((size_t)b*SLEN + sp)*HH + j] + sigf(vi)*tanhf(vg);
        float h = sigf(vo)*tanhf(c);
        g_sh[((size_t)b*SLEN + sp + 1)*HH + j] = h;
        g_sc[((size_t)b*SLEN + sp + 1)*HH + j] = c;
        g_h1[b*HH+j] = h;
        g_c1[b*HH+j] = c;
    }
}

// ------------------- decode kernel B: word cell -------------------
__global__ __launch_bounds__(256) void decodeB(int t,
    const float* __restrict__ word_Wih, const float* __restrict__ word_Whh,
    const float* __restrict__ word_b)
{
    __shared__ float hs[32][64], ws[32][64];
    __shared__ int wp_s[BB];
    const int tid = threadIdx.x;
    if (tid < BB) wp_s[tid] = g_wpa[t*BB + tid];
    __syncthreads();
    const int j0 = blockIdx.x << 4;
    const int lrow = tid >> 2;
    const int wr = (lrow&3)*HH + j0 + (lrow>>2);
    float acc[4][4] = {};
    // seg0: h1 . word_Wih[:, :768]
    accum_seg(acc, g_h1 + lrow*HH, word_Wih + (size_t)wr*(2*HH), hs, ws, tid);
    // seg1: c1 . word_Wih[:, 768:]
    accum_seg(acc, g_c1 + lrow*HH, word_Wih + (size_t)wr*(2*HH) + HH, hs, ws, tid);
    // seg2: wh_prev (gathered) . word_Whh
    accum_seg(acc, g_wh + ((size_t)lrow*WLEN + wp_s[lrow])*HH, word_Whh + (size_t)wr*HH, hs, ws, tid);
    const int jj = tid & 15, mg = tid >> 4;
    const int j = j0 + jj;
    #pragma unroll
    for (int mi=0; mi<4; mi++) {
        int b = (mg<<2) + mi;
        int wp = wp_s[b];
        float vi = word_b[j]        + acc[mi][0];
        float vf = word_b[HH + j]   + acc[mi][1];
        float vg = word_b[2*HH + j] + acc[mi][2];
        float vo = word_b[3*HH + j] + acc[mi][3];
        float c = sigf(vf)*g_wc[((size_t)b*WLEN + wp)*HH + j] + sigf(vi)*tanhf(vg);
        float h = sigf(vo)*tanhf(c);
        g_wh[((size_t)b*WLEN + wp + 1)*HH + j] = h;
        g_wc[((size_t)b*WLEN + wp + 1)*HH + j] = c;
        g_whbuf[b*HH+j] = h;
    }
}

// ------------------- x_cur classifier half precompute + first-row init ---------
__global__ void ccur_kernel(const float* __restrict__ clsW, const float* __restrict__ clsb,
                            float* __restrict__ out)
{
    int gt = blockIdx.x*blockDim.x + threadIdx.x;
    int gw = gt >> 5, lane = gt & 31;
    if (gw < TT*BB*2) {
        int t = gw >> 7, rem = gw & 127, b = rem >> 1, c = rem & 1;
        const float* x = g_lstm_out + ((size_t)b*SS + t + 1)*(2*HH);
        const float* w = clsW + c*(3*HH) + HH;   // x_cur part: cols [768,2304)
        float s = 0.f;
        for (int k = lane; k < 2*HH; k += 32) s += x[k]*w[k];
        #pragma unroll
        for (int o = 16; o; o >>= 1) s += __shfl_xor_sync(0xffffffffu, s, o);
        if (lane == 0) g_ccur[gw] = s + clsb[c];
    }
    if (gt < 128) {
        int b = gt >> 1, c = gt & 1;
        out[(size_t)b*SS*2 + c] = c ? 1.f : -1.f;
    }
}

// ------------------- final classifier (step TT-1 -> out position 255) ---------
__global__ void final_cls(const float* __restrict__ clsW, float* __restrict__ out)
{
    int tid = threadIdx.x;
    if (tid < 128) {
        int b = tid >> 1, c = tid & 1;
        const float* w = clsW + c*(3*HH);
        const float* hb = g_whbuf + b*HH;
        float s = g_ccur[(TT-1)*BB*2 + (b<<1) + c];
        for (int k = 0; k < HH; k++) s += hb[k]*w[k];
        out[((size_t)b*SS + TT)*2 + c] = s;
    }
}

// ------------------- launch -------------------
extern "C" void kernel_launch(void* const* d_in, const int* in_sizes, int n_in,
                              void* d_out, int out_size)
{
    // Detect input ordering: dict order has golds (64*256 int32) at index 1,
    // signature order has it last.
    const int dictOrder = (in_sizes[1] == BB*SS);
    const float* hsin = (const float*)d_in[0];
    const int* golds;
    const float *Wih_f,*Whh_f,*b_f,*Wih_b,*Whh_b,*b_b;
    const float *subw_Wih,*subw_Whh,*subw_b,*word_Wih,*word_Whh,*word_b,*clsW,*clsb;
    if (dictOrder) {
        golds    = (const int*)  d_in[1];
        Wih_f    = (const float*)d_in[2];  Whh_f   = (const float*)d_in[3];
        b_f      = (const float*)d_in[4];  Wih_b   = (const float*)d_in[5];
        Whh_b    = (const float*)d_in[6];  b_b     = (const float*)d_in[7];
        subw_Wih = (const float*)d_in[8];  subw_Whh= (const float*)d_in[9];
        subw_b   = (const float*)d_in[10]; word_Wih= (const float*)d_in[11];
        word_Whh = (const float*)d_in[12]; word_b  = (const float*)d_in[13];
        clsW     = (const float*)d_in[14]; clsb    = (const float*)d_in[15];
    } else {
        Wih_f    = (const float*)d_in[1];  Whh_f   = (const float*)d_in[2];
        b_f      = (const float*)d_in[3];  Wih_b   = (const float*)d_in[4];
        Whh_b    = (const float*)d_in[5];  b_b     = (const float*)d_in[6];
        subw_Wih = (const float*)d_in[7];  subw_Whh= (const float*)d_in[8];
        subw_b   = (const float*)d_in[9];  word_Wih= (const float*)d_in[10];
        word_Whh = (const float*)d_in[11]; word_b  = (const float*)d_in[12];
        clsW     = (const float*)d_in[13]; clsb    = (const float*)d_in[14];
        golds    = (const int*)  d_in[15];
    }
    float* out = (float*)d_out;

    float *p_gif, *p_gib, *p_lo, *p_pre1;
    cudaGetSymbolAddress((void**)&p_gif,  g_gi_f);
    cudaGetSymbolAddress((void**)&p_gib,  g_gi_b);
    cudaGetSymbolAddress((void**)&p_lo,   g_lstm_out);
    cudaGetSymbolAddress((void**)&p_pre1, g_pre1);

    zero_states<<<96, 256>>>();
    ptr_kernel<<<1, 64>>>(golds);

    // input-gate precompute for both directions: (B*S,768)@(768,3072)+b
    gemm_xw<<<dim3(48, 256), 256>>>(hsin, Wih_f, b_f, p_gif, HH);
    gemm_xw<<<dim3(48, 256), 256>>>(hsin, Wih_b, b_b, p_gib, HH);

    // sequential BiLSTM recurrence
    for (int t = 0; t < SS; t++)
        lstm_step<<<dim3(48, 2), 256>>>(t, Whh_f, Whh_b);

    // subword input precompute: (255*64,1536)@(1536,3072)+b
    gemm_xw<<<dim3(48, TT), 256>>>(p_lo, subw_Wih, subw_b, p_pre1, 2*HH);

    // classifier x_cur halves + first output row
    ccur_kernel<<<4080, 256>>>(clsW, clsb, out);

    // sequential decode
    for (int t = 0; t < TT; t++) {
        decodeA<<<49, 256>>>(t, subw_Whh, clsW, out);
        decodeB<<<48, 256>>>(t, word_Wih, word_Whh, word_b);
    }
    final_cls<<<1, 128>>>(clsW, out);
}